// round 3
// baseline (speedup 1.0000x reference)
#include <cuda_runtime.h>
#include <stdint.h>

#define N_NODES_MAX 100000
#define IN_FEAT 64
#define OUT_FEAT 64
#define NUM_BASES 4
#define PROJ_COLS (NUM_BASES * OUT_FEAT)   // 256
#define TOT_COLS (PROJ_COLS + OUT_FEAT)    // 320

// Scratch: projected node features, [N, 4*64] fp32 (~102.4 MB)
__device__ float g_proj[(size_t)N_NODES_MAX * PROJ_COLS];

// ---------------------------------------------------------------------------
// Kernel A: fused GEMM
//   cols 0..255   -> g_proj[n, b*64+o] = sum_k feat[n,k] * weight[b,k,o]
//   cols 256..319 -> out[n, o] = h_bias[o] + sum_k feat[n,k] * loop_w[k,o]
// 64x64 block tile, 4x4 register microtile, K=64 (whole reduction in smem).
// ---------------------------------------------------------------------------
__global__ __launch_bounds__(256) void rgcn_gemm_kernel(
    const float* __restrict__ feat,      // [N, 64]
    const float* __restrict__ weight,    // [4, 64, 64]
    const float* __restrict__ loop_w,    // [64, 64]
    const float* __restrict__ h_bias,    // [64]
    float* __restrict__ out,             // [N, 64]
    int n_nodes)
{
    __shared__ __align__(16) float sA[IN_FEAT][68];  // transposed feat tile sA[k][r]
    __shared__ __align__(16) float sB[IN_FEAT][64];  // weight tile sB[k][c]

    const int row0 = blockIdx.x * 64;
    const int tid = threadIdx.x;

    // Load 64x64 feat tile, transposed into sA[k][r]
    #pragma unroll
    for (int i = tid; i < 64 * 64; i += 256) {
        int r = i >> 6;
        int k = i & 63;
        int row = row0 + r;
        float v = 0.0f;
        if (row < n_nodes) v = feat[(size_t)row * IN_FEAT + k];
        sA[k][r] = v;
    }

    const int tx = tid & 15;   // col group (4 cols)
    const int ty = tid >> 4;   // row group (4 rows)

    for (int ct = 0; ct < TOT_COLS / 64; ++ct) {
        __syncthreads();
        // Load B tile for cols [ct*64, ct*64+64)
        #pragma unroll
        for (int i = tid; i < 64 * 64; i += 256) {
            int k = i >> 6;
            int c = i & 63;
            int col = ct * 64 + c;
            float w;
            if (col < PROJ_COLS) {
                int b = col >> 6;
                int o = col & 63;
                w = weight[((size_t)b * 64 + k) * 64 + o];
            } else {
                w = loop_w[(size_t)k * 64 + (col - PROJ_COLS)];
            }
            sB[k][c] = w;
        }
        __syncthreads();

        float acc[4][4] = {};
        #pragma unroll
        for (int k = 0; k < 64; ++k) {
            float4 a = *(const float4*)&sA[k][ty * 4];
            float4 b = *(const float4*)&sB[k][tx * 4];
            acc[0][0] += a.x * b.x; acc[0][1] += a.x * b.y; acc[0][2] += a.x * b.z; acc[0][3] += a.x * b.w;
            acc[1][0] += a.y * b.x; acc[1][1] += a.y * b.y; acc[1][2] += a.y * b.z; acc[1][3] += a.y * b.w;
            acc[2][0] += a.z * b.x; acc[2][1] += a.z * b.y; acc[2][2] += a.z * b.z; acc[2][3] += a.z * b.w;
            acc[3][0] += a.w * b.x; acc[3][1] += a.w * b.y; acc[3][2] += a.w * b.z; acc[3][3] += a.w * b.w;
        }

        // Store
        if (ct < 4) {
            int colbase = ct * 64 + tx * 4;
            #pragma unroll
            for (int i = 0; i < 4; ++i) {
                int row = row0 + ty * 4 + i;
                if (row < n_nodes) {
                    float4 v = make_float4(acc[i][0], acc[i][1], acc[i][2], acc[i][3]);
                    *(float4*)&g_proj[(size_t)row * PROJ_COLS + colbase] = v;
                }
            }
        } else {
            int colbase = tx * 4;
            float b0 = h_bias[colbase + 0];
            float b1 = h_bias[colbase + 1];
            float b2 = h_bias[colbase + 2];
            float b3 = h_bias[colbase + 3];
            #pragma unroll
            for (int i = 0; i < 4; ++i) {
                int row = row0 + ty * 4 + i;
                if (row < n_nodes) {
                    float4 v = make_float4(acc[i][0] + b0, acc[i][1] + b1,
                                           acc[i][2] + b2, acc[i][3] + b3);
                    *(float4*)&out[(size_t)row * OUT_FEAT + colbase] = v;
                }
            }
        }
    }
}

// ---------------------------------------------------------------------------
// Kernel B: per-edge gather/combine/scatter
//   msg = (sum_b w_comp[etype,b] * proj[src, b, :]) * norm
//   out[dst, :] += msg   (red.global.add.v4.f32)
// 16 threads per edge, each owning 4 contiguous output features.
// NOTE: src/dst/etypes are int32 on device (JAX x64 disabled downcasts int64).
// ---------------------------------------------------------------------------
__global__ __launch_bounds__(256) void rgcn_edge_kernel(
    const int* __restrict__ src,
    const int* __restrict__ dst,
    const int* __restrict__ etypes,
    const float* __restrict__ norm,      // [E, 1]
    const float* __restrict__ w_comp,    // [8, 4]
    float* __restrict__ out,             // [N, 64]
    int n_edges)
{
    int idx = blockIdx.x * blockDim.x + threadIdx.x;
    int e = idx >> 4;
    int lane = idx & 15;
    if (e >= n_edges) return;

    int s = __ldg(&src[e]);
    int d = __ldg(&dst[e]);
    int t = __ldg(&etypes[e]);
    float nm = __ldg(&norm[e]);

    float4 cw = __ldg((const float4*)(w_comp + t * NUM_BASES));
    float c0 = cw.x * nm;
    float c1 = cw.y * nm;
    float c2 = cw.z * nm;
    float c3 = cw.w * nm;

    const float4* p = (const float4*)(g_proj + (size_t)s * PROJ_COLS);
    // basis b lives at float offset b*64 = float4 offset b*16
    float4 v0 = __ldg(&p[lane]);
    float4 v1 = __ldg(&p[16 + lane]);
    float4 v2 = __ldg(&p[32 + lane]);
    float4 v3 = __ldg(&p[48 + lane]);

    float4 m;
    m.x = c0 * v0.x + c1 * v1.x + c2 * v2.x + c3 * v3.x;
    m.y = c0 * v0.y + c1 * v1.y + c2 * v2.y + c3 * v3.y;
    m.z = c0 * v0.z + c1 * v1.z + c2 * v2.z + c3 * v3.z;
    m.w = c0 * v0.w + c1 * v1.w + c2 * v2.w + c3 * v3.w;

    float* o = out + (size_t)d * OUT_FEAT + lane * 4;
    asm volatile("red.global.add.v4.f32 [%0], {%1, %2, %3, %4};"
                 :: "l"(o), "f"(m.x), "f"(m.y), "f"(m.z), "f"(m.w)
                 : "memory");
}

// ---------------------------------------------------------------------------
extern "C" void kernel_launch(void* const* d_in, const int* in_sizes, int n_in,
                              void* d_out, int out_size)
{
    const float* feat    = (const float*)d_in[0];
    const int*   src     = (const int*)d_in[1];
    const int*   dst     = (const int*)d_in[2];
    const int*   etypes  = (const int*)d_in[3];
    const float* norm    = (const float*)d_in[4];
    const float* weight  = (const float*)d_in[5];
    const float* w_comp  = (const float*)d_in[6];
    const float* h_bias  = (const float*)d_in[7];
    const float* loop_w  = (const float*)d_in[8];
    float*       out     = (float*)d_out;

    int n_nodes = in_sizes[0] / IN_FEAT;
    int n_edges = in_sizes[1];

    // Phase 1: projections + self-loop/bias init of out
    int gemm_blocks = (n_nodes + 63) / 64;
    rgcn_gemm_kernel<<<gemm_blocks, 256>>>(feat, weight, loop_w, h_bias, out, n_nodes);

    // Phase 2: edge message + aggregation
    long long total_threads = (long long)n_edges * 16;
    int edge_blocks = (int)((total_threads + 255) / 256);
    rgcn_edge_kernel<<<edge_blocks, 256>>>(src, dst, etypes, norm, w_comp, out, n_edges);
}